// round 16
// baseline (speedup 1.0000x reference)
#include <cuda_runtime.h>
#include <cuda_bf16.h>
#include <cstdint>

#define NN 50000   // nodes
#define MM 10000   // hyperedges
#define EE 500000  // incidence pairs (max)
#define DD 128     // feature dim

// ---------------- static scratch ----------------
__device__ float g_emean[MM * DD];   // per-hyperedge mean of x    5.1 MB (fully written)
__device__ float g_eproj[MM * DD];   // emean @ Wveu               5.1 MB
__device__ float g_wvu  [DD * DD];   // W_v @ W_u_top
__device__ float g_wveu [DD * DD];   // W_v @ W_e @ W_u_bot
__device__ int   g_ecnt [MM];
__device__ int   g_ncnt [NN];
__device__ int   g_eofs [MM];
__device__ int   g_nofs [NN];
__device__ int   g_ecur [MM];
__device__ int   g_ncur [NN];
__device__ int   g_ecsr [EE];        // node ids grouped (unordered) by hyperedge
__device__ int   g_ncsr [EE];        // hyperedge ids grouped (unordered) by node
__device__ int   g_etot;
__device__ int   g_ntot;

// ---------------- zero counters ----------------
__global__ void k_zero() {
    int i = blockIdx.x * blockDim.x + threadIdx.x;
    int stride = gridDim.x * blockDim.x;
    for (int j = i; j < NN; j += stride) g_ncnt[j] = 0;
    for (int j = i; j < MM; j += stride) g_ecnt[j] = 0;
    if (i == 0) { g_etot = 0; g_ntot = 0; }
}

// ---------------- one-sided histogram, int4-vectorized ----------------
__global__ void k_hist_vec(const int* __restrict__ idx, int* __restrict__ cnt, int E) {
    const int tid = blockIdx.x * blockDim.x + threadIdx.x;
    const int stride = gridDim.x * blockDim.x;
    const int E4 = E >> 2;
    const int4* idx4 = (const int4*)idx;
    for (int q = tid; q < E4; q += stride) {
        int4 v = __ldg(&idx4[q]);
        atomicAdd(&cnt[v.x], 1);
        atomicAdd(&cnt[v.y], 1);
        atomicAdd(&cnt[v.z], 1);
        atomicAdd(&cnt[v.w], 1);
    }
    // tail
    for (int e = E4 * 4 + tid; e < E; e += stride)
        atomicAdd(&cnt[__ldg(&idx[e])], 1);
}
// scalar fallback (unaligned base)
__global__ void k_hist_scalar(const int* __restrict__ idx, int* __restrict__ cnt, int E) {
    const int tid = blockIdx.x * blockDim.x + threadIdx.x;
    const int stride = gridDim.x * blockDim.x;
    for (int e = tid; e < E; e += stride)
        atomicAdd(&cnt[__ldg(&idx[e])], 1);
}

// ---------------- scan-free segment offsets (warp-aggregated, one side) ----------------
__global__ void k_offsets(const int* __restrict__ cnt, int* __restrict__ ofs,
                          int* __restrict__ cur, int* __restrict__ tot, int n) {
    int i = blockIdx.x * blockDim.x + threadIdx.x;
    int lane = threadIdx.x & 31;
    int c = (i < n) ? cnt[i] : 0;
    int s = c;
#pragma unroll
    for (int o = 1; o < 32; o <<= 1) {
        int t = __shfl_up_sync(0xffffffffu, s, o);
        if (lane >= o) s += t;
    }
    int warpTotal = __shfl_sync(0xffffffffu, s, 31);
    int base = 0;
    if (lane == 31) base = atomicAdd(tot, warpTotal);
    base = __shfl_sync(0xffffffffu, base, 31);
    if (i < n) {
        int beg = base + s - c;
        ofs[i] = beg;
        cur[i] = beg;
    }
}

// ---------------- one-sided CSR placement, int4-vectorized ----------------
__global__ void k_place_vec(const int* __restrict__ key, const int* __restrict__ val,
                            int* __restrict__ cur, int* __restrict__ csr, int E) {
    const int tid = blockIdx.x * blockDim.x + threadIdx.x;
    const int stride = gridDim.x * blockDim.x;
    const int E4 = E >> 2;
    const int4* key4 = (const int4*)key;
    const int4* val4 = (const int4*)val;
    for (int q = tid; q < E4; q += stride) {
        int4 k = __ldg(&key4[q]);
        int4 v = __ldg(&val4[q]);
        csr[atomicAdd(&cur[k.x], 1)] = v.x;
        csr[atomicAdd(&cur[k.y], 1)] = v.y;
        csr[atomicAdd(&cur[k.z], 1)] = v.z;
        csr[atomicAdd(&cur[k.w], 1)] = v.w;
    }
    for (int e = E4 * 4 + tid; e < E; e += stride)
        csr[atomicAdd(&cur[__ldg(&key[e])], 1)] = __ldg(&val[e]);
}
__global__ void k_place_scalar(const int* __restrict__ key, const int* __restrict__ val,
                               int* __restrict__ cur, int* __restrict__ csr, int E) {
    const int tid = blockIdx.x * blockDim.x + threadIdx.x;
    const int stride = gridDim.x * blockDim.x;
    for (int e = tid; e < E; e += stride)
        csr[atomicAdd(&cur[__ldg(&key[e])], 1)] = __ldg(&val[e]);
}

// ---------------- weight combos: Wvu = Wv@Wu_top ; Wveu = Wv@We@Wu_bot ----------------
__global__ void __launch_bounds__(128) k_combo(
    const float* __restrict__ Wv, const float* __restrict__ We,
    const float* __restrict__ Wu)
{
    __shared__ float rowv[DD];
    __shared__ float tmp[DD];
    const int c = threadIdx.x;
    const int b = blockIdx.x;
    const float* Wu_top = Wu;
    const float* Wu_bot = Wu + DD * DD;

    if (b < DD) {
        const int r = b;
        rowv[c] = Wv[r * DD + c];
        __syncthreads();
        float a0 = 0.f, a1 = 0.f;
#pragma unroll
        for (int k = 0; k < DD; k += 2) {
            a0 = fmaf(rowv[k],     Wu_top[(k)     * DD + c], a0);
            a1 = fmaf(rowv[k + 1], Wu_top[(k + 1) * DD + c], a1);
        }
        g_wvu[r * DD + c] = a0 + a1;
    } else {
        const int r = b - DD;
        rowv[c] = Wv[r * DD + c];
        __syncthreads();
        float a0 = 0.f, a1 = 0.f;
#pragma unroll
        for (int k = 0; k < DD; k += 2) {
            a0 = fmaf(rowv[k],     We[(k)     * DD + c], a0);
            a1 = fmaf(rowv[k + 1], We[(k + 1) * DD + c], a1);
        }
        tmp[c] = a0 + a1;
        __syncthreads();
        float b0 = 0.f, b1 = 0.f;
#pragma unroll
        for (int k = 0; k < DD; k += 2) {
            b0 = fmaf(tmp[k],     Wu_bot[(k)     * DD + c], b0);
            b1 = fmaf(tmp[k + 1], Wu_bot[(k + 1) * DD + c], b1);
        }
        g_wveu[r * DD + c] = b0 + b1;
    }
}

// ---------------- L2-only vector load ----------------
__device__ __forceinline__ float4 ldcg_v4(const float* p) {
    float4 v;
    asm volatile("ld.global.cg.v4.f32 {%0,%1,%2,%3}, [%4];"
                 : "=f"(v.x), "=f"(v.y), "=f"(v.z), "=f"(v.w) : "l"(p));
    return v;
}

// ---------------- gather_e: per-hyperedge mean of raw x ----------------
__global__ void k_gather_e(const float* __restrict__ x) {
    const int lane = threadIdx.x & 31;
    const int seg = (blockIdx.x * blockDim.x + threadIdx.x) >> 5;
    if (seg >= MM) return;
    const int beg = g_eofs[seg];
    const int cnt = g_ecnt[seg];
    const int end = beg + cnt;
    float4 acc = make_float4(0.f, 0.f, 0.f, 0.f);
    int i = beg;
    for (; i + 1 < end; i += 2) {
        int r0 = __ldg(&g_ecsr[i]);
        int r1 = __ldg(&g_ecsr[i + 1]);
        float4 v0 = ldcg_v4(&x[(size_t)r0 * DD + lane * 4]);
        float4 v1 = ldcg_v4(&x[(size_t)r1 * DD + lane * 4]);
        acc.x += v0.x + v1.x; acc.y += v0.y + v1.y;
        acc.z += v0.z + v1.z; acc.w += v0.w + v1.w;
    }
    if (i < end) {
        int r0 = __ldg(&g_ecsr[i]);
        float4 v0 = ldcg_v4(&x[(size_t)r0 * DD + lane * 4]);
        acc.x += v0.x; acc.y += v0.y; acc.z += v0.z; acc.w += v0.w;
    }
    float inv = 1.0f / fmaxf((float)cnt, 1.0f);
    acc.x *= inv; acc.y *= inv; acc.z *= inv; acc.w *= inv;
    *(float4*)&g_emean[(size_t)seg * DD + lane * 4] = acc;
}

// ---------------- gather_n: per-node mean of eproj + fused relu epilogue ----------------
__global__ void k_gather_n(float* __restrict__ out, int N) {
    const int lane = threadIdx.x & 31;
    const int seg = (blockIdx.x * blockDim.x + threadIdx.x) >> 5;
    if (seg >= N) return;
    const int beg = g_nofs[seg];
    const int cnt = g_ncnt[seg];
    const int end = beg + cnt;
    float4 acc = make_float4(0.f, 0.f, 0.f, 0.f);
    int i = beg;
    for (; i + 1 < end; i += 2) {
        int c0 = __ldg(&g_ncsr[i]);
        int c1 = __ldg(&g_ncsr[i + 1]);
        float4 v0 = ldcg_v4(&g_eproj[(size_t)c0 * DD + lane * 4]);
        float4 v1 = ldcg_v4(&g_eproj[(size_t)c1 * DD + lane * 4]);
        acc.x += v0.x + v1.x; acc.y += v0.y + v1.y;
        acc.z += v0.z + v1.z; acc.w += v0.w + v1.w;
    }
    if (i < end) {
        int c0 = __ldg(&g_ncsr[i]);
        float4 v0 = ldcg_v4(&g_eproj[(size_t)c0 * DD + lane * 4]);
        acc.x += v0.x; acc.y += v0.y; acc.z += v0.z; acc.w += v0.w;
    }
    float inv = 1.0f / fmaxf((float)cnt, 1.0f);
    float4 o = *(const float4*)&out[(size_t)seg * DD + lane * 4];
    o.x = fmaxf(fmaf(acc.x, inv, o.x), 0.0f);
    o.y = fmaxf(fmaf(acc.y, inv, o.y), 0.0f);
    o.z = fmaxf(fmaf(acc.z, inv, o.z), 0.0f);
    o.w = fmaxf(fmaf(acc.w, inv, o.w), 0.0f);
    *(float4*)&out[(size_t)seg * DD + lane * 4] = o;
}

// ---------------- packed f32x2 FMA helpers ----------------
__device__ __forceinline__ unsigned long long pack_dup(float a) {
    unsigned long long r;
    uint32_t u = __float_as_uint(a);
    asm("mov.b64 %0, {%1, %1};" : "=l"(r) : "r"(u));
    return r;
}
__device__ __forceinline__ void fma_x2(unsigned long long& acc,
                                       unsigned long long a, unsigned long long b) {
    asm("fma.rn.f32x2 %0, %1, %2, %0;" : "+l"(acc) : "l"(a), "l"(b));
}
__device__ __forceinline__ float2 unpack_x2(unsigned long long v) {
    float2 r;
    uint32_t lo, hi;
    asm("mov.b64 {%0, %1}, %2;" : "=r"(lo), "=r"(hi) : "l"(v));
    r.x = __uint_as_float(lo);
    r.y = __uint_as_float(hi);
    return r;
}

// ---------------- double-buffered SGEMM body (f32x2 inner loop) ----------------
template <bool BIAS>
__device__ __forceinline__ void gemm_body(
    const float* __restrict__ A0, const float* __restrict__ Bm,
    const float* __restrict__ bias, float* __restrict__ C, int Mrows)
{
    __shared__ float As[2][16][132];
    __shared__ __align__(16) float Bs[2][16][128];

    const int tid = threadIdx.x;
    const int ty = tid >> 4;
    const int tx = tid & 15;
    const int rowBase = blockIdx.x * 128;

    const int aRow = tid >> 2;
    const int aCol = (tid & 3) << 2;
    const int bRow = tid >> 5;
    const int bCol = (tid & 31) << 2;

    unsigned long long acc2[8][4];
#pragma unroll
    for (int i = 0; i < 8; i++)
#pragma unroll
        for (int j = 0; j < 4; j++) acc2[i][j] = 0ull;

    float4 pa[2], pb[2];
#pragma unroll
    for (int p = 0; p < 2; p++) {
        int gr = rowBase + aRow + p * 64;
        pa[p] = make_float4(0.f, 0.f, 0.f, 0.f);
        if (gr < Mrows) pa[p] = *(const float4*)&A0[(size_t)gr * DD + aCol];
        pb[p] = *(const float4*)&Bm[(size_t)(bRow + p * 8) * DD + bCol];
    }
#pragma unroll
    for (int p = 0; p < 2; p++) {
        int r = aRow + p * 64;
        As[0][aCol + 0][r] = pa[p].x;
        As[0][aCol + 1][r] = pa[p].y;
        As[0][aCol + 2][r] = pa[p].z;
        As[0][aCol + 3][r] = pa[p].w;
        *(float4*)&Bs[0][bRow + p * 8][bCol] = pb[p];
    }
    __syncthreads();

#pragma unroll
    for (int kb = 0; kb < 8; kb++) {
        if (kb < 7) {
            const int ko = (kb + 1) * 16;
#pragma unroll
            for (int p = 0; p < 2; p++) {
                int gr = rowBase + aRow + p * 64;
                pa[p] = make_float4(0.f, 0.f, 0.f, 0.f);
                if (gr < Mrows) pa[p] = *(const float4*)&A0[(size_t)gr * DD + ko + aCol];
                pb[p] = *(const float4*)&Bm[(size_t)(ko + bRow + p * 8) * DD + bCol];
            }
        }
        const int cb = kb & 1;
#pragma unroll
        for (int k = 0; k < 16; k++) {
            float ar[8];
            *(float4*)&ar[0] = *(const float4*)&As[cb][k][ty * 8];
            *(float4*)&ar[4] = *(const float4*)&As[cb][k][ty * 8 + 4];
            const unsigned long long* bp =
                (const unsigned long long*)&Bs[cb][k][tx * 8];
            unsigned long long br2[4];
            br2[0] = bp[0]; br2[1] = bp[1]; br2[2] = bp[2]; br2[3] = bp[3];
#pragma unroll
            for (int i = 0; i < 8; i++) {
                unsigned long long ai = pack_dup(ar[i]);
#pragma unroll
                for (int j = 0; j < 4; j++) fma_x2(acc2[i][j], ai, br2[j]);
            }
        }
        if (kb < 7) {
            const int nb = cb ^ 1;
#pragma unroll
            for (int p = 0; p < 2; p++) {
                int r = aRow + p * 64;
                As[nb][aCol + 0][r] = pa[p].x;
                As[nb][aCol + 1][r] = pa[p].y;
                As[nb][aCol + 2][r] = pa[p].z;
                As[nb][aCol + 3][r] = pa[p].w;
                *(float4*)&Bs[nb][bRow + p * 8][bCol] = pb[p];
            }
            __syncthreads();
        }
    }

#pragma unroll
    for (int i = 0; i < 8; i++) {
        int gr = rowBase + ty * 8 + i;
        if (gr >= Mrows) continue;
#pragma unroll
        for (int j = 0; j < 4; j += 2) {
            float2 v0 = unpack_x2(acc2[i][j]);
            float2 v1 = unpack_x2(acc2[i][j + 1]);
            float4 v = make_float4(v0.x, v0.y, v1.x, v1.y);
            int gc = tx * 8 + j * 2;
            if (BIAS) {
                v.x += __ldg(&bias[gc + 0]);
                v.y += __ldg(&bias[gc + 1]);
                v.z += __ldg(&bias[gc + 2]);
                v.w += __ldg(&bias[gc + 3]);
            }
            *(float4*)&C[(size_t)gr * DD + gc] = v;
        }
    }
}

__global__ void __launch_bounds__(256, 2) k_gemm_bias(
    const float* A, const float* B, const float* bias, float* C, int Mrows)
{
    gemm_body<true>(A, B, bias, C, Mrows);
}

__global__ void __launch_bounds__(256, 2) k_gemm_plain(
    const float* A, const float* B, float* C, int Mrows)
{
    gemm_body<false>(A, B, nullptr, C, Mrows);
}

// ---------------- launch ----------------
extern "C" void kernel_launch(void* const* d_in, const int* in_sizes, int n_in,
                              void* d_out, int out_size)
{
    const float* x   = (const float*)d_in[0];
    const int*   ei  = (const int*)  d_in[1];
    const float* Wv  = (const float*)d_in[2];
    const float* We  = (const float*)d_in[3];
    const float* Wu  = (const float*)d_in[4];
    const float* bu  = (const float*)d_in[5];
    float* out = (float*)d_out;

    const int E = in_sizes[1] / 2;
    const int N = in_sizes[0] / DD;
    const int* rowp = ei;
    const int* colp = ei + E;

    float* emean; cudaGetSymbolAddress((void**)&emean, g_emean);
    float* eproj; cudaGetSymbolAddress((void**)&eproj, g_eproj);
    float* wvu;   cudaGetSymbolAddress((void**)&wvu,   g_wvu);
    float* wveu;  cudaGetSymbolAddress((void**)&wveu,  g_wveu);
    int *ecnt, *ncnt, *eofs, *nofs, *ecur, *ncur, *ecsr, *ncsr, *etot, *ntot;
    cudaGetSymbolAddress((void**)&ecnt, g_ecnt);
    cudaGetSymbolAddress((void**)&ncnt, g_ncnt);
    cudaGetSymbolAddress((void**)&eofs, g_eofs);
    cudaGetSymbolAddress((void**)&nofs, g_nofs);
    cudaGetSymbolAddress((void**)&ecur, g_ecur);
    cudaGetSymbolAddress((void**)&ncur, g_ncur);
    cudaGetSymbolAddress((void**)&ecsr, g_ecsr);
    cudaGetSymbolAddress((void**)&ncsr, g_ncsr);
    cudaGetSymbolAddress((void**)&etot, g_etot);
    cudaGetSymbolAddress((void**)&ntot, g_ntot);

    const bool vecOK = ((((uintptr_t)rowp | (uintptr_t)colp) & 15u) == 0u);

    cudaStream_t side1, side2;
    cudaStreamCreateWithFlags(&side1, cudaStreamNonBlocking);
    cudaStreamCreateWithFlags(&side2, cudaStreamNonBlocking);
    cudaEvent_t evEntry, evZero, evGemm, evNcsr;
    cudaEventCreateWithFlags(&evEntry, cudaEventDisableTiming);
    cudaEventCreateWithFlags(&evZero,  cudaEventDisableTiming);
    cudaEventCreateWithFlags(&evGemm,  cudaEventDisableTiming);
    cudaEventCreateWithFlags(&evNcsr,  cudaEventDisableTiming);

    // side1 (forks at entry): combo -> out = x@Wvu + bias
    cudaEventRecord(evEntry, 0);
    cudaStreamWaitEvent(side1, evEntry, 0);
    k_combo<<<256, 128, 0, side1>>>(Wv, We, Wu);
    k_gemm_bias<<<(N + 127) / 128, 256, 0, side1>>>(x, wvu, bu, out, N);
    cudaEventRecord(evGemm, side1);

    // main: zero counters
    k_zero<<<64, 256>>>();
    cudaEventRecord(evZero, 0);

    // side2 (after zero): node-side CSR build (hist_n -> offs_n -> place_n)
    cudaStreamWaitEvent(side2, evZero, 0);
    if (vecOK) k_hist_vec<<<1024, 256, 0, side2>>>(rowp, ncnt, E);
    else       k_hist_scalar<<<2048, 256, 0, side2>>>(rowp, ncnt, E);
    k_offsets<<<(NN + 255) / 256, 256, 0, side2>>>(ncnt, nofs, ncur, ntot, NN);
    if (vecOK) k_place_vec<<<1024, 256, 0, side2>>>(rowp, colp, ncur, ncsr, E);
    else       k_place_scalar<<<2048, 256, 0, side2>>>(rowp, colp, ncur, ncsr, E);
    cudaEventRecord(evNcsr, side2);

    // main: edge-side CSR build -> gather_e -> gemm
    if (vecOK) k_hist_vec<<<1024, 256>>>(colp, ecnt, E);
    else       k_hist_scalar<<<2048, 256>>>(colp, ecnt, E);
    k_offsets<<<(MM + 255) / 256, 256>>>(ecnt, eofs, ecur, etot, MM);
    if (vecOK) k_place_vec<<<1024, 256>>>(colp, rowp, ecur, ecsr, E);
    else       k_place_scalar<<<2048, 256>>>(colp, rowp, ecur, ecsr, E);
    k_gather_e<<<(MM * 32 + 255) / 256, 256>>>(x);
    k_gemm_plain<<<(MM + 127) / 128, 256>>>(emean, wveu, eproj, MM);

    // join node CSR + side GEMM, then fused gather + relu epilogue
    cudaStreamWaitEvent(0, evNcsr, 0);
    cudaStreamWaitEvent(0, evGemm, 0);
    k_gather_n<<<(N * 32 + 255) / 256, 256>>>(out, N);

    cudaEventDestroy(evEntry);
    cudaEventDestroy(evZero);
    cudaEventDestroy(evGemm);
    cudaEventDestroy(evNcsr);
    cudaStreamDestroy(side1);
    cudaStreamDestroy(side2);
}